// round 13
// baseline (speedup 1.0000x reference)
#include <cuda_runtime.h>
#include <cuda_bf16.h>
#include <cstdint>

#define NN 100000      // nodes
#define NE 1600000     // edges
#define NE4 (NE/4)     // 400000
#define DD 32          // feature dim
#define NC 8           // float4 chunks per node row (DD/4)

// Device-global scratch (allocation is forbidden).
__device__ float4 g_y1[NN * NC];
__device__ float4 g_y2[NN * NC];
__device__ float4 g_y3[NN * NC];
__device__ int4   g_rec[NE];     // packed edge records {row*NC, col*NC, val_bits, 0}

// ---------------------------------------------------------------------------
// pack edges into 16B records; precompute row*NC / col*NC to kill IMADs in
// the hot loop. Grid covers NE exactly (6250 * 256).
// ---------------------------------------------------------------------------
__global__ void k_pack(const int* __restrict__ erow, const int* __restrict__ ecol,
                       const float* __restrict__ eval, int4* __restrict__ rec) {
    int e = blockIdx.x * blockDim.x + threadIdx.x;
    rec[e] = make_int4(erow[e] * NC, ecol[e] * NC,
                       __float_as_int(eval[e]), 0);
}

// ---------------------------------------------------------------------------
// zero all three accumulation targets in one pass (exactly NN*NC threads)
// ---------------------------------------------------------------------------
__global__ void k_zero3(float4* __restrict__ a, float4* __restrict__ b,
                        float4* __restrict__ c) {
    int i = blockIdx.x * blockDim.x + threadIdx.x;
    const float4 z = make_float4(0.f, 0.f, 0.f, 0.f);
    a[i] = z;
    b[i] = z;
    c[i] = z;
}

// ---------------------------------------------------------------------------
// COO SpMM over packed records, 4 edges per thread.
//   thread -> chunk c of edges e, e+NE4, e+2*NE4, e+3*NE4.
// All 8 lanes of a group load the same 16B record (HW broadcast); a warp's 4
// records are consecutive (64B, one line) -> 1 L1 wavefront, zero shfls.
// Grid = NE4*NC threads = 3.2M (12,500 * 256): exact, full warps.
// ---------------------------------------------------------------------------
__global__ void k_spmm(const int4* __restrict__ rec,
                       const float4* __restrict__ h, float4* __restrict__ y) {
    int t = blockIdx.x * blockDim.x + threadIdx.x;
    int e = t >> 3;            // base edge index (0 .. NE4-1)
    int c = t & 7;             // float4 chunk within the 32-float feature row

    int4 r[4];
#pragma unroll
    for (int k = 0; k < 4; k++) r[k] = rec[e + k * NE4];   // broadcast loads

    float4 hv[4];              // four independent gathers in flight
#pragma unroll
    for (int k = 0; k < 4; k++) hv[k] = h[r[k].y + c];

#pragma unroll
    for (int k = 0; k < 4; k++) {
        float v = __int_as_float(r[k].z);
        float4 m = make_float4(v * hv[k].x, v * hv[k].y,
                               v * hv[k].z, v * hv[k].w);
        float4* dst = &y[r[k].x + c];
        asm volatile("red.global.add.v4.f32 [%0], {%1, %2, %3, %4};"
                     :: "l"(dst), "f"(m.x), "f"(m.y), "f"(m.z), "f"(m.w)
                     : "memory");
    }
}

// ---------------------------------------------------------------------------
// final combine: out = 0.25 * (x + y1 + y2 + y3)  (single pass)
// ---------------------------------------------------------------------------
__global__ void k_final(float4* __restrict__ out, const float4* __restrict__ x,
                        const float4* __restrict__ a, const float4* __restrict__ b,
                        const float4* __restrict__ c) {
    int i = blockIdx.x * blockDim.x + threadIdx.x;
    float4 xv = x[i], av = a[i], bv = b[i], cv = c[i];
    out[i] = make_float4((xv.x + av.x + bv.x + cv.x) * 0.25f,
                         (xv.y + av.y + bv.y + cv.y) * 0.25f,
                         (xv.z + av.z + bv.z + cv.z) * 0.25f,
                         (xv.w + av.w + bv.w + cv.w) * 0.25f);
}

extern "C" void kernel_launch(void* const* d_in, const int* in_sizes, int n_in,
                              void* d_out, int out_size) {
    const int*    erow = (const int*)  d_in[0];
    const int*    ecol = (const int*)  d_in[1];
    const float*  eval = (const float*)d_in[2];
    const float4* x    = (const float4*)d_in[3];
    float4* out        = (float4*)d_out;

    float4 *y1, *y2, *y3;
    int4* rec;
    cudaGetSymbolAddress((void**)&y1,  g_y1);
    cudaGetSymbolAddress((void**)&y2,  g_y2);
    cudaGetSymbolAddress((void**)&y3,  g_y3);
    cudaGetSymbolAddress((void**)&rec, g_rec);

    const int nodeBlocks = (NN * NC) / 256;    // 3125, exact
    const int packBlocks = NE / 256;           // 6250, exact
    const int edgeBlocks = (NE4 * NC) / 256;   // 12500, exact

    k_pack <<<packBlocks, 256>>>(erow, ecol, eval, rec);
    k_zero3<<<nodeBlocks, 256>>>(y1, y2, y3);
    k_spmm <<<edgeBlocks, 256>>>(rec, x,  y1);   // y1 = A x
    k_spmm <<<edgeBlocks, 256>>>(rec, y1, y2);   // y2 = A y1
    k_spmm <<<edgeBlocks, 256>>>(rec, y2, y3);   // y3 = A y2
    k_final<<<nodeBlocks, 256>>>(out, x, y1, y2, y3);
}

// round 16
// speedup vs baseline: 1.1808x; 1.1808x over previous
#include <cuda_runtime.h>
#include <cuda_bf16.h>
#include <cstdint>

#define NN 100000      // nodes
#define NE 1600000     // edges
#define DD 32          // feature dim
#define NC 8           // float4 chunks per node row (DD/4)
#define NSCAN 98       // ceil(NN/1024)

// Device-global scratch (allocation is forbidden).
__device__ float4 g_y1[NN * NC];
__device__ float4 g_y2[NN * NC];
__device__ float4 g_y3[NN * NC];
__device__ int    g_deg[NN];
__device__ int    g_tmp[NN];
__device__ int    g_blk[128];
__device__ int    g_cursor[NN];
__device__ int4   g_rec[NE];     // row-sorted records {row*NC, col*NC, val_bits, 0}

// ---------------------------------------------------------------------------
// zero y1/y2/y3 (NN*NC float4) and deg (first NN threads). 800K threads exact.
// ---------------------------------------------------------------------------
__global__ void k_zero(float4* __restrict__ a, float4* __restrict__ b,
                       float4* __restrict__ c, int* __restrict__ deg) {
    int i = blockIdx.x * blockDim.x + threadIdx.x;
    const float4 z = make_float4(0.f, 0.f, 0.f, 0.f);
    a[i] = z; b[i] = z; c[i] = z;
    if (i < NN) deg[i] = 0;
}

// ---------------------------------------------------------------------------
// row-degree histogram (grid covers NE exactly)
// ---------------------------------------------------------------------------
__global__ void k_hist(const int* __restrict__ erow, int* __restrict__ deg) {
    int e = blockIdx.x * blockDim.x + threadIdx.x;
    atomicAdd(&deg[erow[e]], 1);
}

// ---------------------------------------------------------------------------
// per-block (1024-wide) exclusive scan of deg -> tmp; block totals -> blk
// ---------------------------------------------------------------------------
__global__ void k_scan1(const int* __restrict__ deg, int* __restrict__ tmp,
                        int* __restrict__ blk) {
    __shared__ int sh[1024];
    int t = threadIdx.x;
    int i = blockIdx.x * 1024 + t;
    int v = (i < NN) ? deg[i] : 0;
    sh[t] = v;
    __syncthreads();
    for (int off = 1; off < 1024; off <<= 1) {
        int add = (t >= off) ? sh[t - off] : 0;
        __syncthreads();
        sh[t] += add;
        __syncthreads();
    }
    if (i < NN) tmp[i] = sh[t] - v;          // exclusive within block
    if (t == 1023) blk[blockIdx.x] = sh[t];  // block total
}

// ---------------------------------------------------------------------------
// combine: cursor[i] = tmp[i] + sum(blk[0..b-1]).  256-thread blocks; all i in
// a block share b = blockIdx.x>>2 (256 | 1024). Warp 0 reduces the <=97 totals.
// ---------------------------------------------------------------------------
__global__ void k_scan2(const int* __restrict__ tmp, const int* __restrict__ blk,
                        int* __restrict__ cursor) {
    __shared__ int s_off;
    int b = blockIdx.x >> 2;
    if (threadIdx.x < 32) {
        int sum = 0;
        for (int j = threadIdx.x; j < b; j += 32) sum += blk[j];
        for (int o = 16; o; o >>= 1) sum += __shfl_down_sync(0xffffffffu, sum, o);
        if (threadIdx.x == 0) s_off = sum;
    }
    __syncthreads();
    int i = blockIdx.x * 256 + threadIdx.x;
    if (i < NN) cursor[i] = tmp[i] + s_off;
}

// ---------------------------------------------------------------------------
// scatter edges into row-sorted slots (grid covers NE exactly)
// ---------------------------------------------------------------------------
__global__ void k_scatter(const int* __restrict__ erow, const int* __restrict__ ecol,
                          const float* __restrict__ eval,
                          int* __restrict__ cursor, int4* __restrict__ rec) {
    int e = blockIdx.x * blockDim.x + threadIdx.x;
    int r = erow[e];
    int p = atomicAdd(&cursor[r], 1);
    rec[p] = make_int4(r * NC, ecol[e] * NC, __float_as_int(eval[e]), 0);
}

// ---------------------------------------------------------------------------
// SpMM over row-sorted records: each 8-lane group handles 4 CONSECUTIVE edges
// (chunk c each); same-row neighbors are merged in registers before RED.
// Grid = (NE/4)*8 threads = 3.2M (12,500 * 256): exact, full warps.
// ---------------------------------------------------------------------------
__device__ __forceinline__ void f4add(float4& a, const float4& b) {
    a.x += b.x; a.y += b.y; a.z += b.z; a.w += b.w;
}
__device__ __forceinline__ void redv4(float4* dst, const float4& m) {
    asm volatile("red.global.add.v4.f32 [%0], {%1, %2, %3, %4};"
                 :: "l"(dst), "f"(m.x), "f"(m.y), "f"(m.z), "f"(m.w)
                 : "memory");
}

__global__ void k_spmm(const int4* __restrict__ rec,
                       const float4* __restrict__ h, float4* __restrict__ y) {
    int t = blockIdx.x * blockDim.x + threadIdx.x;
    int g = t >> 3;            // edge-quad index (0 .. NE/4-1)
    int c = t & 7;             // float4 chunk within the feature row
    int base = g << 2;         // 4 consecutive sorted edges

    int4 r0 = rec[base + 0];   // 8-lane broadcast loads, 64B/group contiguous
    int4 r1 = rec[base + 1];
    int4 r2 = rec[base + 2];
    int4 r3 = rec[base + 3];

    float4 h0 = h[r0.y + c];   // four independent gathers in flight
    float4 h1 = h[r1.y + c];
    float4 h2 = h[r2.y + c];
    float4 h3 = h[r3.y + c];

    float v0 = __int_as_float(r0.z), v1 = __int_as_float(r1.z);
    float v2 = __int_as_float(r2.z), v3 = __int_as_float(r3.z);
    float4 m0 = make_float4(v0*h0.x, v0*h0.y, v0*h0.z, v0*h0.w);
    float4 m1 = make_float4(v1*h1.x, v1*h1.y, v1*h1.z, v1*h1.w);
    float4 m2 = make_float4(v2*h2.x, v2*h2.y, v2*h2.z, v2*h2.w);
    float4 m3 = make_float4(v3*h3.x, v3*h3.y, v3*h3.z, v3*h3.w);

    // merge same-row runs (sorted: equal rows are adjacent)
    float4 acc = m0; int cur = r0.x;
    if (r1.x == cur) f4add(acc, m1);
    else { redv4(&y[cur + c], acc); acc = m1; cur = r1.x; }
    if (r2.x == cur) f4add(acc, m2);
    else { redv4(&y[cur + c], acc); acc = m2; cur = r2.x; }
    if (r3.x == cur) f4add(acc, m3);
    else { redv4(&y[cur + c], acc); acc = m3; cur = r3.x; }
    redv4(&y[cur + c], acc);
}

// ---------------------------------------------------------------------------
// final combine: out = 0.25 * (x + y1 + y2 + y3)
// ---------------------------------------------------------------------------
__global__ void k_final(float4* __restrict__ out, const float4* __restrict__ x,
                        const float4* __restrict__ a, const float4* __restrict__ b,
                        const float4* __restrict__ c) {
    int i = blockIdx.x * blockDim.x + threadIdx.x;
    float4 xv = x[i], av = a[i], bv = b[i], cv = c[i];
    out[i] = make_float4((xv.x + av.x + bv.x + cv.x) * 0.25f,
                         (xv.y + av.y + bv.y + cv.y) * 0.25f,
                         (xv.z + av.z + bv.z + cv.z) * 0.25f,
                         (xv.w + av.w + bv.w + cv.w) * 0.25f);
}

extern "C" void kernel_launch(void* const* d_in, const int* in_sizes, int n_in,
                              void* d_out, int out_size) {
    const int*    erow = (const int*)  d_in[0];
    const int*    ecol = (const int*)  d_in[1];
    const float*  eval = (const float*)d_in[2];
    const float4* x    = (const float4*)d_in[3];
    float4* out        = (float4*)d_out;

    float4 *y1, *y2, *y3; int *deg, *tmp, *blk, *cursor; int4* rec;
    cudaGetSymbolAddress((void**)&y1,     g_y1);
    cudaGetSymbolAddress((void**)&y2,     g_y2);
    cudaGetSymbolAddress((void**)&y3,     g_y3);
    cudaGetSymbolAddress((void**)&deg,    g_deg);
    cudaGetSymbolAddress((void**)&tmp,    g_tmp);
    cudaGetSymbolAddress((void**)&blk,    g_blk);
    cudaGetSymbolAddress((void**)&cursor, g_cursor);
    cudaGetSymbolAddress((void**)&rec,    g_rec);

    const int nodeBlocks = (NN * NC) / 256;      // 3125, exact
    const int edgeBlocks = NE / 256;             // 6250, exact
    const int spmmBlocks = (NE / 4) * 8 / 256;   // 12500, exact
    const int combBlocks = (NN + 255) / 256;     // 391

    k_zero   <<<nodeBlocks, 256>>>(y1, y2, y3, deg);
    k_hist   <<<edgeBlocks, 256>>>(erow, deg);
    k_scan1  <<<NSCAN, 1024>>>(deg, tmp, blk);
    k_scan2  <<<combBlocks, 256>>>(tmp, blk, cursor);
    k_scatter<<<edgeBlocks, 256>>>(erow, ecol, eval, cursor, rec);

    k_spmm   <<<spmmBlocks, 256>>>(rec, x,  y1);   // y1 = A x
    k_spmm   <<<spmmBlocks, 256>>>(rec, y1, y2);   // y2 = A y1
    k_spmm   <<<spmmBlocks, 256>>>(rec, y2, y3);   // y3 = A y2
    k_final  <<<nodeBlocks, 256>>>(out, x, y1, y2, y3);
}

// round 17
// speedup vs baseline: 1.1812x; 1.0003x over previous
#include <cuda_runtime.h>
#include <cuda_bf16.h>
#include <cstdint>

#define NN 100000      // nodes
#define NE 1600000     // edges
#define DD 32          // feature dim
#define NC 8           // float4 chunks per node row (DD/4)
#define NSCAN 98       // ceil(NN/1024)

// Device-global scratch (allocation is forbidden).
__device__ float4 g_y1[NN * NC];
__device__ float4 g_y2[NN * NC];
__device__ float4 g_y3[NN * NC];
__device__ int    g_deg[NN];
__device__ int    g_cursor[NN];
__device__ int    g_base;        // global allocation counter for block bases
__device__ int4   g_rec[NE];     // row-grouped records {row*NC, col*NC, val_bits, 0}

// ---------------------------------------------------------------------------
// zero y1/y2/y3 (NN*NC float4), deg (first NN threads), g_base (thread 0).
// 800K threads exact.
// ---------------------------------------------------------------------------
__global__ void k_zero(float4* __restrict__ a, float4* __restrict__ b,
                       float4* __restrict__ c, int* __restrict__ deg,
                       int* __restrict__ basep) {
    int i = blockIdx.x * blockDim.x + threadIdx.x;
    const float4 z = make_float4(0.f, 0.f, 0.f, 0.f);
    a[i] = z; b[i] = z; c[i] = z;
    if (i < NN) deg[i] = 0;
    if (i == 0) *basep = 0;
}

// ---------------------------------------------------------------------------
// row-degree histogram (grid covers NE exactly)
// ---------------------------------------------------------------------------
__global__ void k_hist(const int* __restrict__ erow, int* __restrict__ deg) {
    int e = blockIdx.x * blockDim.x + threadIdx.x;
    atomicAdd(&deg[erow[e]], 1);
}

// ---------------------------------------------------------------------------
// fused scan: per-block exclusive scan of deg + atomic block base.
// Row regions are contiguous per row; their global ORDER is nondeterministic
// (atomic), which only permutes fp summation order.
// ---------------------------------------------------------------------------
__global__ void k_scan(const int* __restrict__ deg, int* __restrict__ cursor,
                       int* __restrict__ basep) {
    __shared__ int sh[1024];
    __shared__ int s_base;
    int t = threadIdx.x;
    int i = blockIdx.x * 1024 + t;
    int v = (i < NN) ? deg[i] : 0;
    sh[t] = v;
    __syncthreads();
    for (int off = 1; off < 1024; off <<= 1) {
        int add = (t >= off) ? sh[t - off] : 0;
        __syncthreads();
        sh[t] += add;
        __syncthreads();
    }
    if (t == 1023) s_base = atomicAdd(basep, sh[1023]);   // block total
    __syncthreads();
    if (i < NN) cursor[i] = s_base + sh[t] - v;           // exclusive + base
}

// ---------------------------------------------------------------------------
// scatter edges into row-grouped slots (grid covers NE exactly)
// ---------------------------------------------------------------------------
__global__ void k_scatter(const int* __restrict__ erow, const int* __restrict__ ecol,
                          const float* __restrict__ eval,
                          int* __restrict__ cursor, int4* __restrict__ rec) {
    int e = blockIdx.x * blockDim.x + threadIdx.x;
    int r = erow[e];
    int p = atomicAdd(&cursor[r], 1);
    rec[p] = make_int4(r * NC, ecol[e] * NC, __float_as_int(eval[e]), 0);
}

// ---------------------------------------------------------------------------
// SpMM over row-grouped records: each 8-lane group handles 8 CONSECUTIVE
// edges (chunk c each) in two 4-gather rounds; same-row neighbors merged in
// registers before RED, accumulator carried across rounds.
// Grid = (NE/8)*8 threads = 1.6M (6,250 * 256): exact, full warps.
// ---------------------------------------------------------------------------
__device__ __forceinline__ void f4add(float4& a, const float4& b) {
    a.x += b.x; a.y += b.y; a.z += b.z; a.w += b.w;
}
__device__ __forceinline__ void redv4(float4* dst, const float4& m) {
    asm volatile("red.global.add.v4.f32 [%0], {%1, %2, %3, %4};"
                 :: "l"(dst), "f"(m.x), "f"(m.y), "f"(m.z), "f"(m.w)
                 : "memory");
}

__global__ void k_spmm(const int4* __restrict__ rec,
                       const float4* __restrict__ h, float4* __restrict__ y) {
    int t = blockIdx.x * blockDim.x + threadIdx.x;
    int g = t >> 3;            // 8-edge group index (0 .. NE/8-1)
    int c = t & 7;             // float4 chunk within the feature row
    int base = g << 3;         // 8 consecutive row-grouped edges

    float4 acc; int cur;

#pragma unroll
    for (int round = 0; round < 2; round++) {
        int b = base + round * 4;
        int4 r0 = rec[b + 0];      // broadcast loads, 64B/group contiguous
        int4 r1 = rec[b + 1];
        int4 r2 = rec[b + 2];
        int4 r3 = rec[b + 3];

        float4 h0 = h[r0.y + c];   // four independent gathers in flight
        float4 h1 = h[r1.y + c];
        float4 h2 = h[r2.y + c];
        float4 h3 = h[r3.y + c];

        float v0 = __int_as_float(r0.z), v1 = __int_as_float(r1.z);
        float v2 = __int_as_float(r2.z), v3 = __int_as_float(r3.z);
        float4 m0 = make_float4(v0*h0.x, v0*h0.y, v0*h0.z, v0*h0.w);
        float4 m1 = make_float4(v1*h1.x, v1*h1.y, v1*h1.z, v1*h1.w);
        float4 m2 = make_float4(v2*h2.x, v2*h2.y, v2*h2.z, v2*h2.w);
        float4 m3 = make_float4(v3*h3.x, v3*h3.y, v3*h3.z, v3*h3.w);

        if (round == 0) { acc = m0; cur = r0.x; }
        else {
            if (r0.x == cur) f4add(acc, m0);
            else { redv4(&y[cur + c], acc); acc = m0; cur = r0.x; }
        }
        if (r1.x == cur) f4add(acc, m1);
        else { redv4(&y[cur + c], acc); acc = m1; cur = r1.x; }
        if (r2.x == cur) f4add(acc, m2);
        else { redv4(&y[cur + c], acc); acc = m2; cur = r2.x; }
        if (r3.x == cur) f4add(acc, m3);
        else { redv4(&y[cur + c], acc); acc = m3; cur = r3.x; }
    }
    redv4(&y[cur + c], acc);
}

// ---------------------------------------------------------------------------
// final combine: out = 0.25 * (x + y1 + y2 + y3)
// ---------------------------------------------------------------------------
__global__ void k_final(float4* __restrict__ out, const float4* __restrict__ x,
                        const float4* __restrict__ a, const float4* __restrict__ b,
                        const float4* __restrict__ c) {
    int i = blockIdx.x * blockDim.x + threadIdx.x;
    float4 xv = x[i], av = a[i], bv = b[i], cv = c[i];
    out[i] = make_float4((xv.x + av.x + bv.x + cv.x) * 0.25f,
                         (xv.y + av.y + bv.y + cv.y) * 0.25f,
                         (xv.z + av.z + bv.z + cv.z) * 0.25f,
                         (xv.w + av.w + bv.w + cv.w) * 0.25f);
}

extern "C" void kernel_launch(void* const* d_in, const int* in_sizes, int n_in,
                              void* d_out, int out_size) {
    const int*    erow = (const int*)  d_in[0];
    const int*    ecol = (const int*)  d_in[1];
    const float*  eval = (const float*)d_in[2];
    const float4* x    = (const float4*)d_in[3];
    float4* out        = (float4*)d_out;

    float4 *y1, *y2, *y3; int *deg, *cursor, *basep; int4* rec;
    cudaGetSymbolAddress((void**)&y1,     g_y1);
    cudaGetSymbolAddress((void**)&y2,     g_y2);
    cudaGetSymbolAddress((void**)&y3,     g_y3);
    cudaGetSymbolAddress((void**)&deg,    g_deg);
    cudaGetSymbolAddress((void**)&cursor, g_cursor);
    cudaGetSymbolAddress((void**)&basep,  g_base);
    cudaGetSymbolAddress((void**)&rec,    g_rec);

    const int nodeBlocks = (NN * NC) / 256;      // 3125, exact
    const int edgeBlocks = NE / 256;             // 6250, exact
    const int spmmBlocks = NE / 256;             // 6250 (NE/8 groups * 8 lanes / 256)

    k_zero   <<<nodeBlocks, 256>>>(y1, y2, y3, deg, basep);
    k_hist   <<<edgeBlocks, 256>>>(erow, deg);
    k_scan   <<<NSCAN, 1024>>>(deg, cursor, basep);
    k_scatter<<<edgeBlocks, 256>>>(erow, ecol, eval, cursor, rec);

    k_spmm   <<<spmmBlocks, 256>>>(rec, x,  y1);   // y1 = A x
    k_spmm   <<<spmmBlocks, 256>>>(rec, y1, y2);   // y2 = A y1
    k_spmm   <<<spmmBlocks, 256>>>(rec, y2, y3);   // y3 = A y2
    k_final  <<<nodeBlocks, 256>>>(out, x, y1, y2, y3);
}